// round 1
// baseline (speedup 1.0000x reference)
#include <cuda_runtime.h>

#define BB 4
#define LL 1024
#define DD 64
#define UU 32

// Scratch (allocation-free per harness rules)
__device__ float g_q [BB*LL*UU];   // q = x @ Wt               (512 KB)
__device__ float g_kp[BB*LL*UU];   // k' = x @ Wx + bh         (512 KB)

__device__ __forceinline__ float tanh_fast(float x) {
    float y;
    asm("tanh.approx.f32 %0, %1;" : "=f"(y) : "f"(x));
    return y;
}

// ---------------------------------------------------------------------------
// Kernel 1: projections. 8 rows per block, one thread per (row, u).
// ---------------------------------------------------------------------------
__global__ __launch_bounds__(256) void prep_kernel(
    const float* __restrict__ x,
    const float* __restrict__ Wt,
    const float* __restrict__ Wx,
    const float* __restrict__ bh)
{
    __shared__ float sWt[DD*UU];
    __shared__ float sWx[DD*UU];
    __shared__ float sx [8*DD];
    int t = threadIdx.x;
    for (int idx = t; idx < DD*UU; idx += 256) { sWt[idx] = Wt[idx]; sWx[idx] = Wx[idx]; }
    int row0 = blockIdx.x * 8;
    for (int idx = t; idx < 8*DD; idx += 256) sx[idx] = x[row0*DD + idx];
    __syncthreads();

    int r = t >> 5, u = t & 31;
    float aq = 0.f, ak = 0.f;
    #pragma unroll
    for (int d = 0; d < DD; d++) {
        float xv = sx[r*DD + d];
        aq = fmaf(xv, sWt[d*UU + u], aq);
        ak = fmaf(xv, sWx[d*UU + u], ak);
    }
    int row = row0 + r;
    g_q [row*UU + u] = aq;
    g_kp[row*UU + u] = ak + bh[u];
}

// ---------------------------------------------------------------------------
// Kernel 2: fused scoring + softmax + value gather. One block per (b, i).
// ---------------------------------------------------------------------------
__global__ __launch_bounds__(256) void attn_kernel(
    const float* __restrict__ x,
    const float* __restrict__ Wa,
    float* __restrict__ out)
{
    __shared__ float e_sh[LL];     // scores, then exp(scores - m)
    __shared__ float sq  [UU];
    __shared__ float swa [UU];
    __shared__ float red [8];
    __shared__ float vpart[256];

    int t  = threadIdx.x;
    int bi = blockIdx.x;           // bi = b*1024 + i
    int b  = bi >> 10;

    const float* kp = g_kp + b * (LL*UU);

    if (t < UU) { sq[t] = g_q[bi*UU + t]; swa[t] = Wa[t]; }
    __syncthreads();

    float q[UU];
    #pragma unroll
    for (int u = 0; u < UU; u++) q[u] = sq[u];

    // --- Pass 1: e[j] = sum_u Wa[u]*tanh(q[u] + kp[j][u]) -------------------
    float ev[4];
    float lmax = -1e30f;
    #pragma unroll
    for (int jj = 0; jj < 4; jj++) {
        int j = jj*256 + t;
        const float4* kr = (const float4*)(kp + j*UU);
        float acc = 0.f;
        #pragma unroll
        for (int c = 0; c < 8; c++) {
            float4 kv = kr[c];
            acc = fmaf(tanh_fast(q[4*c+0] + kv.x), swa[4*c+0], acc);
            acc = fmaf(tanh_fast(q[4*c+1] + kv.y), swa[4*c+1], acc);
            acc = fmaf(tanh_fast(q[4*c+2] + kv.z), swa[4*c+2], acc);
            acc = fmaf(tanh_fast(q[4*c+3] + kv.w), swa[4*c+3], acc);
        }
        ev[jj] = acc;
        lmax = fmaxf(lmax, acc);
    }

    // --- block max reduce ---------------------------------------------------
    #pragma unroll
    for (int o = 16; o; o >>= 1) lmax = fmaxf(lmax, __shfl_xor_sync(0xffffffffu, lmax, o));
    if ((t & 31) == 0) red[t >> 5] = lmax;
    __syncthreads();
    float m = red[0];
    #pragma unroll
    for (int w = 1; w < 8; w++) m = fmaxf(m, red[w]);
    __syncthreads();                         // red reuse below

    // --- exp + block sum reduce ---------------------------------------------
    float lsum = 0.f;
    #pragma unroll
    for (int jj = 0; jj < 4; jj++) {
        float e = __expf(ev[jj] - m);
        e_sh[jj*256 + t] = e;
        lsum += e;
    }
    #pragma unroll
    for (int o = 16; o; o >>= 1) lsum += __shfl_xor_sync(0xffffffffu, lsum, o);
    if ((t & 31) == 0) red[t >> 5] = lsum;
    __syncthreads();                         // also orders e_sh writes
    float s = 0.f;
    #pragma unroll
    for (int w = 0; w < 8; w++) s += red[w];
    float inv = 1.f / (s + 1e-8f);

    // --- Pass 2: v[d] = (sum_j ex[j] * x[b,j,d]) * inv ----------------------
    int d = t & 63, g = t >> 6;              // 64 d-lanes x 4 j-groups
    const float* xb = x + b * (LL*DD);
    float acc = 0.f;
    int j0 = g * 256;
    #pragma unroll 8
    for (int j = j0; j < j0 + 256; j++)
        acc = fmaf(e_sh[j], xb[j*DD + d], acc);
    vpart[t] = acc;
    __syncthreads();
    if (t < DD) {
        float v = vpart[t] + vpart[64 + t] + vpart[128 + t] + vpart[192 + t];
        out[bi*DD + t] = v * inv;
    }
}

// ---------------------------------------------------------------------------
extern "C" void kernel_launch(void* const* d_in, const int* in_sizes, int n_in,
                              void* d_out, int out_size)
{
    const float* x  = (const float*)d_in[0];   // inputs (B,L,D)
    const float* Wt = (const float*)d_in[1];   // (D,U)
    const float* Wx = (const float*)d_in[2];   // (D,U)
    const float* Wa = (const float*)d_in[3];   // (U,1)
    const float* bh = (const float*)d_in[4];   // (U,)
    // d_in[5] = ba: cancels in softmax (shift-invariant). d_in[6]: dead code.

    prep_kernel<<<BB*LL/8, 256>>>(x, Wt, Wx, bh);
    attn_kernel<<<BB*LL, 256>>>(x, Wa, (float*)d_out);
}

// round 2
// speedup vs baseline: 3.3960x; 3.3960x over previous
#include <cuda_runtime.h>
#include <cuda_fp16.h>

#define BB 4
#define LL 1024
#define DD 64
#define UU 32

// Scratch (allocation-free): transposed half2-packed k' and packed q.
// g_kpt[(b*4 + cc)*1024 + j] : uint4 = u-indices [cc*8 .. cc*8+7] of row (b,j)
__device__ uint4    g_kpt[4*BB*LL];
__device__ unsigned g_qh [BB*LL*16];   // row*16 + c : u-pair (2c, 2c+1)

__device__ __forceinline__ unsigned tanh2u(unsigned x) {
    unsigned y; asm("tanh.approx.f16x2 %0, %1;" : "=r"(y) : "r"(x)); return y;
}
__device__ __forceinline__ unsigned hadd2u(unsigned a, unsigned b) {
    __half2 r = __hadd2(reinterpret_cast<__half2&>(a), reinterpret_cast<__half2&>(b));
    return reinterpret_cast<unsigned&>(r);
}
__device__ __forceinline__ unsigned packh2(float a, float b) {
    __half2 h = __floats2half2_rn(a, b);
    return reinterpret_cast<unsigned&>(h);
}
__device__ __forceinline__ float2 h2f2(unsigned a) {
    return __half22float2(reinterpret_cast<__half2&>(a));
}

// ---------------------------------------------------------------------------
// Kernel 1: projections -> packed/transposed half scratch. 8 rows per block.
// ---------------------------------------------------------------------------
__global__ __launch_bounds__(256) void prep_kernel(
    const float* __restrict__ x,
    const float* __restrict__ Wt,
    const float* __restrict__ Wx,
    const float* __restrict__ bh)
{
    __shared__ float sWt[DD*UU];
    __shared__ float sWx[DD*UU];
    __shared__ float sx [8*DD];
    __shared__ float sq [8][UU];
    __shared__ float sk [8][UU];
    int t = threadIdx.x;
    for (int idx = t; idx < DD*UU; idx += 256) { sWt[idx] = Wt[idx]; sWx[idx] = Wx[idx]; }
    int row0 = blockIdx.x * 8;
    for (int idx = t; idx < 8*DD; idx += 256) sx[idx] = x[row0*DD + idx];
    __syncthreads();

    int r = t >> 5, u = t & 31;
    float aq = 0.f, ak = 0.f;
    #pragma unroll
    for (int d = 0; d < DD; d++) {
        float xv = sx[r*DD + d];
        aq = fmaf(xv, sWt[d*UU + u], aq);
        ak = fmaf(xv, sWx[d*UU + u], ak);
    }
    sq[r][u] = aq;
    sk[r][u] = ak + bh[u];
    __syncthreads();

    if (t < 128) {                       // pack q: 8 rows x 16 half2
        int rr = t >> 4, c = t & 15;
        g_qh[(row0 + rr)*16 + c] = packh2(sq[rr][2*c], sq[rr][2*c+1]);
    }
    if (t < 32) {                        // pack + transpose k': 8 rows x 4 chunks
        int rr = t >> 2, cc = t & 3;
        int row = row0 + rr;
        int b = row >> 10, j = row & 1023;
        uint4 v;
        v.x = packh2(sk[rr][cc*8+0], sk[rr][cc*8+1]);
        v.y = packh2(sk[rr][cc*8+2], sk[rr][cc*8+3]);
        v.z = packh2(sk[rr][cc*8+4], sk[rr][cc*8+5]);
        v.w = packh2(sk[rr][cc*8+6], sk[rr][cc*8+7]);
        g_kpt[(b*4 + cc)*1024 + j] = v;
    }
}

// ---------------------------------------------------------------------------
// Kernel 2: fused scoring + softmax + value gather. One block per 2 rows.
// ---------------------------------------------------------------------------
__global__ void attn_kernel(
    const float* __restrict__ x,
    const float* __restrict__ Wa,
    float* __restrict__ out)
{
    __shared__ float e0_sh[LL];
    __shared__ float e1_sh[LL];
    __shared__ float vsh0 [LL];          // 16 groups x 64 d partials
    __shared__ float vsh1 [LL];
    __shared__ float red0[8], red1[8];

    int t   = threadIdx.x;
    int bi  = blockIdx.x;                // 0..2047
    int b   = bi >> 9;
    int row0 = b*LL + (bi & 511)*2;      // global row of i0 (i1 = row0+1)

    // uniform loads -> registers
    unsigned q0h[16], q1h[16];
    float wa[UU];
    #pragma unroll
    for (int c = 0; c < 16; c++) {
        q0h[c] = g_qh[ row0   *16 + c];
        q1h[c] = g_qh[(row0+1)*16 + c];
    }
    #pragma unroll
    for (int u = 0; u < UU; u++) wa[u] = Wa[u];

    const uint4* kp = g_kpt + (b*4)*1024;

    // --- Pass 1: e, exp, sum (no max pass needed: |e| <= sum|Wa| ~ 2.6) -----
    float s0 = 0.f, s1 = 0.f;
    #pragma unroll
    for (int jj = 0; jj < 4; jj++) {
        int j = jj*256 + t;
        float e0 = 0.f, e1 = 0.f;
        #pragma unroll
        for (int cc = 0; cc < 4; cc++) {
            uint4 kv = kp[cc*1024 + j];
            unsigned kw[4] = {kv.x, kv.y, kv.z, kv.w};
            #pragma unroll
            for (int k = 0; k < 4; k++) {
                int c = cc*4 + k;
                float2 f0 = h2f2(tanh2u(hadd2u(q0h[c], kw[k])));
                float2 f1 = h2f2(tanh2u(hadd2u(q1h[c], kw[k])));
                e0 = fmaf(f0.x, wa[2*c], e0); e0 = fmaf(f0.y, wa[2*c+1], e0);
                e1 = fmaf(f1.x, wa[2*c], e1); e1 = fmaf(f1.y, wa[2*c+1], e1);
            }
        }
        float x0 = __expf(e0), x1 = __expf(e1);
        e0_sh[j] = x0; e1_sh[j] = x1;
        s0 += x0; s1 += x1;
    }

    // --- block sum reduce (both rows) ---------------------------------------
    #pragma unroll
    for (int o = 16; o; o >>= 1) {
        s0 += __shfl_xor_sync(0xffffffffu, s0, o);
        s1 += __shfl_xor_sync(0xffffffffu, s1, o);
    }
    if ((t & 31) == 0) { red0[t >> 5] = s0; red1[t >> 5] = s1; }
    __syncthreads();                     // also orders e_sh for pass 2
    float S0 = 0.f, S1 = 0.f;
    #pragma unroll
    for (int w = 0; w < 8; w++) { S0 += red0[w]; S1 += red1[w]; }
    float inv0 = 1.f / S0, inv1 = 1.f / S1;

    // --- Pass 2: v[d] = sum_j p[j] * x[b,j,d], shared across both rows ------
    int d4 = t & 15, g = t >> 4;         // 16 float4 d-lanes x 16 j-groups
    const float4* xb = (const float4*)(x + b*(LL*DD));
    float4 a0 = {0,0,0,0}, a1 = {0,0,0,0};
    #pragma unroll 4
    for (int jj = 0; jj < 64; jj++) {
        int j = jj*16 + g;               // interleaved: adjacent lanes -> adjacent j
        float4 xv = xb[j*16 + d4];
        float p0 = e0_sh[j], p1 = e1_sh[j];
        a0.x = fmaf(p0, xv.x, a0.x); a0.y = fmaf(p0, xv.y, a0.y);
        a0.z = fmaf(p0, xv.z, a0.z); a0.w = fmaf(p0, xv.w, a0.w);
        a1.x = fmaf(p1, xv.x, a1.x); a1.y = fmaf(p1, xv.y, a1.y);
        a1.z = fmaf(p1, xv.z, a1.z); a1.w = fmaf(p1, xv.w, a1.w);
    }
    ((float4*)vsh0)[g*16 + d4] = a0;
    ((float4*)vsh1)[g*16 + d4] = a1;
    __syncthreads();

    if (t < 128) {
        int i = t >> 6, d = t & 63;
        const float* vs = i ? vsh1 : vsh0;
        float v = 0.f;
        #pragma unroll
        for (int gg = 0; gg < 16; gg++) v += vs[gg*64 + d];
        out[(row0 + i)*DD + d] = v * (i ? inv1 : inv0);
    }
}

// ---------------------------------------------------------------------------
extern "C" void kernel_launch(void* const* d_in, const int* in_sizes, int n_in,
                              void* d_out, int out_size)
{
    const float* x  = (const float*)d_in[0];
    const float* Wt = (const float*)d_in[1];
    const float* Wx = (const float*)d_in[2];
    const float* Wa = (const float*)d_in[3];
    const float* bh = (const float*)d_in[4];
    // d_in[5] = ba cancels in softmax; d_in[6] attention_width is dead code.

    prep_kernel<<<BB*LL/8, 256>>>(x, Wt, Wx, bh);
    attn_kernel<<<BB*LL/2, 256>>>(x, Wa, (float*)d_out);
}

// round 3
// speedup vs baseline: 3.4375x; 1.0122x over previous
#include <cuda_runtime.h>
#include <cuda_fp16.h>

#define BB 4
#define LL 1024
#define DD 64
#define UU 32
#define TI 4

// Scratch (allocation-free): transposed half2-packed k' and packed q.
__device__ uint4    g_kpt[4*BB*LL];    // [(b*4+cc)*1024 + j] : u [cc*8..cc*8+7]
__device__ unsigned g_qh [BB*LL*16];   // row*16 + c : u-pair (2c, 2c+1)

__device__ __forceinline__ unsigned tanh2u(unsigned x) {
    unsigned y; asm("tanh.approx.f16x2 %0, %1;" : "=r"(y) : "r"(x)); return y;
}
__device__ __forceinline__ unsigned hadd2u(unsigned a, unsigned b) {
    __half2 r = __hadd2(reinterpret_cast<__half2&>(a), reinterpret_cast<__half2&>(b));
    return reinterpret_cast<unsigned&>(r);
}
__device__ __forceinline__ unsigned hfma2u(unsigned a, unsigned b, unsigned c) {
    __half2 r = __hfma2(reinterpret_cast<__half2&>(a), reinterpret_cast<__half2&>(b),
                        reinterpret_cast<__half2&>(c));
    return reinterpret_cast<unsigned&>(r);
}
__device__ __forceinline__ unsigned packh2(float a, float b) {
    __half2 h = __floats2half2_rn(a, b);
    return reinterpret_cast<unsigned&>(h);
}
__device__ __forceinline__ float2 h2f2(unsigned a) {
    return __half22float2(reinterpret_cast<__half2&>(a));
}
// Packed fp32x2 (Blackwell FFMA2 — only reachable via PTX)
__device__ __forceinline__ unsigned long long ffma2(
    unsigned long long a, unsigned long long b, unsigned long long c) {
    unsigned long long d;
    asm("fma.rn.f32x2 %0, %1, %2, %3;" : "=l"(d) : "l"(a), "l"(b), "l"(c));
    return d;
}
__device__ __forceinline__ unsigned long long bcast2(float p) {
    unsigned long long d;
    asm("mov.b64 %0, {%1, %1};" : "=l"(d) : "f"(p));
    return d;
}
__device__ __forceinline__ unsigned long long packf2(float a, float b) {
    unsigned long long d;
    asm("mov.b64 %0, {%1, %2};" : "=l"(d) : "f"(a), "f"(b));
    return d;
}

// ---------------------------------------------------------------------------
// Kernel 1: projections -> packed/transposed half scratch. 8 rows per block.
// ---------------------------------------------------------------------------
__global__ __launch_bounds__(256) void prep_kernel(
    const float* __restrict__ x,
    const float* __restrict__ Wt,
    const float* __restrict__ Wx,
    const float* __restrict__ bh)
{
    __shared__ float sWt[DD*UU];
    __shared__ float sWx[DD*UU];
    __shared__ float sx [8*DD];
    __shared__ float sq [8][UU];
    __shared__ float sk [8][UU];
    int t = threadIdx.x;
    for (int idx = t; idx < DD*UU; idx += 256) { sWt[idx] = Wt[idx]; sWx[idx] = Wx[idx]; }
    int row0 = blockIdx.x * 8;
    for (int idx = t; idx < 8*DD; idx += 256) sx[idx] = x[row0*DD + idx];
    __syncthreads();

    int r = t >> 5, u = t & 31;
    float aq = 0.f, ak = 0.f;
    #pragma unroll
    for (int d = 0; d < DD; d++) {
        float xv = sx[r*DD + d];
        aq = fmaf(xv, sWt[d*UU + u], aq);
        ak = fmaf(xv, sWx[d*UU + u], ak);
    }
    sq[r][u] = aq;
    sk[r][u] = ak + bh[u];
    __syncthreads();

    if (t < 128) {
        int rr = t >> 4, c = t & 15;
        g_qh[(row0 + rr)*16 + c] = packh2(sq[rr][2*c], sq[rr][2*c+1]);
    }
    if (t < 32) {
        int rr = t >> 2, cc = t & 3;
        int row = row0 + rr;
        int b = row >> 10, j = row & 1023;
        uint4 v;
        v.x = packh2(sk[rr][cc*8+0], sk[rr][cc*8+1]);
        v.y = packh2(sk[rr][cc*8+2], sk[rr][cc*8+3]);
        v.z = packh2(sk[rr][cc*8+4], sk[rr][cc*8+5]);
        v.w = packh2(sk[rr][cc*8+6], sk[rr][cc*8+7]);
        g_kpt[(b*4 + cc)*1024 + j] = v;
    }
}

// ---------------------------------------------------------------------------
// Kernel 2: fused scoring + softmax + value gather. 4 rows per block.
// ---------------------------------------------------------------------------
__global__ __launch_bounds__(256, 2) void attn_kernel(
    const float* __restrict__ x,
    const float* __restrict__ Wa,
    float* __restrict__ out)
{
    __shared__ float4   p_sh[LL];         // {p_row0..p_row3} per j  (16 KB)
    __shared__ float    vsh [TI*LL];      // partials: [r][g][d]     (16 KB)
    __shared__ float    redv[TI][8];
    __shared__ unsigned swa2[16];

    int t  = threadIdx.x;
    int bi = blockIdx.x;                  // 0..1023
    int b  = bi >> 8;
    int row0 = b*LL + (bi & 255)*TI;

    if (t < 16) swa2[t] = packh2(Wa[2*t], Wa[2*t+1]);

    unsigned qh[TI][16];
    #pragma unroll
    for (int r = 0; r < TI; r++)
        #pragma unroll
        for (int c = 0; c < 16; c++)
            qh[r][c] = g_qh[(row0 + r)*16 + c];
    __syncthreads();

    unsigned wa2[16];
    #pragma unroll
    for (int c = 0; c < 16; c++) wa2[c] = swa2[c];

    const uint4* kp = g_kpt + (b*4)*1024;

    // --- Pass 1: e, exp, sum (no max pass: |e| <= sum|Wa| ~ small) ----------
    float s[TI] = {0.f, 0.f, 0.f, 0.f};
    #pragma unroll
    for (int jj = 0; jj < 4; jj++) {
        int j = jj*256 + t;
        unsigned acc[TI][4];
        #pragma unroll
        for (int r = 0; r < TI; r++)
            #pragma unroll
            for (int k = 0; k < 4; k++) acc[r][k] = 0u;

        #pragma unroll
        for (int cc = 0; cc < 4; cc++) {
            uint4 kv = kp[cc*1024 + j];
            unsigned kw[4] = {kv.x, kv.y, kv.z, kv.w};
            #pragma unroll
            for (int k = 0; k < 4; k++) {
                int c = cc*4 + k;
                #pragma unroll
                for (int r = 0; r < TI; r++) {
                    unsigned th = tanh2u(hadd2u(qh[r][c], kw[k]));
                    acc[r][k] = hfma2u(th, wa2[c], acc[r][k]);
                }
            }
        }
        float4 pj;
        float* pp = (float*)&pj;
        #pragma unroll
        for (int r = 0; r < TI; r++) {
            unsigned s01 = hadd2u(acc[r][0], acc[r][1]);
            unsigned s23 = hadd2u(acc[r][2], acc[r][3]);
            float2 f0 = h2f2(s01), f1 = h2f2(s23);
            float e  = (f0.x + f0.y) + (f1.x + f1.y);
            float ex = __expf(e);
            pp[r] = ex;
            s[r] += ex;
        }
        p_sh[j] = pj;
    }

    // --- block sum reduce (all rows) ----------------------------------------
    #pragma unroll
    for (int o = 16; o; o >>= 1)
        #pragma unroll
        for (int r = 0; r < TI; r++) s[r] += __shfl_xor_sync(0xffffffffu, s[r], o);
    if ((t & 31) == 0)
        #pragma unroll
        for (int r = 0; r < TI; r++) redv[r][t >> 5] = s[r];
    __syncthreads();                      // also orders p_sh for pass 2
    float inv[TI];
    #pragma unroll
    for (int r = 0; r < TI; r++) {
        float S = 0.f;
        #pragma unroll
        for (int w = 0; w < 8; w++) S += redv[r][w];
        inv[r] = 1.f / (S + 1e-8f);
    }

    // --- Pass 2: v[r][d] = sum_j p[r][j] * x[b,j,d] -------------------------
    int d4 = t & 15, g = t >> 4;          // 16 float4 d-lanes x 16 j-groups
    const float4* xb = (const float4*)(x + b*(LL*DD));
    unsigned long long a[TI][2];
    #pragma unroll
    for (int r = 0; r < TI; r++) { a[r][0] = 0ull; a[r][1] = 0ull; }

    #pragma unroll 4
    for (int jj = 0; jj < 64; jj++) {
        int j = jj*16 + g;                // adjacent lanes -> adjacent j rows
        float4 xv = xb[j*16 + d4];
        unsigned long long xlo = packf2(xv.x, xv.y);
        unsigned long long xhi = packf2(xv.z, xv.w);
        float4 pj = p_sh[j];
        float* pp = (float*)&pj;
        #pragma unroll
        for (int r = 0; r < TI; r++) {
            unsigned long long p2 = bcast2(pp[r]);
            a[r][0] = ffma2(p2, xlo, a[r][0]);
            a[r][1] = ffma2(p2, xhi, a[r][1]);
        }
    }
    #pragma unroll
    for (int r = 0; r < TI; r++) {
        float4 av;
        ((unsigned long long*)&av)[0] = a[r][0];
        ((unsigned long long*)&av)[1] = a[r][1];
        ((float4*)vsh)[r*256 + g*16 + d4] = av;
    }
    __syncthreads();

    // --- final combine: 256 threads = 4 rows x 64 d -------------------------
    {
        int r = t >> 6, d = t & 63;
        float v = 0.f;
        #pragma unroll
        for (int gg = 0; gg < 16; gg++) v += vsh[r*LL + gg*64 + d];
        out[(row0 + r)*DD + d] = v * inv[r];
    }
}

// ---------------------------------------------------------------------------
extern "C" void kernel_launch(void* const* d_in, const int* in_sizes, int n_in,
                              void* d_out, int out_size)
{
    const float* x  = (const float*)d_in[0];
    const float* Wt = (const float*)d_in[1];
    const float* Wx = (const float*)d_in[2];
    const float* Wa = (const float*)d_in[3];
    const float* bh = (const float*)d_in[4];
    // d_in[5] = ba cancels in softmax; d_in[6] attention_width is dead code.

    prep_kernel<<<BB*LL/8, 256>>>(x, Wt, Wx, bh);
    attn_kernel<<<BB*LL/TI, 256>>>(x, Wa, (float*)d_out);
}

// round 4
// speedup vs baseline: 3.6348x; 1.0574x over previous
#include <cuda_runtime.h>
#include <cuda_fp16.h>

#define BB 4
#define LL 1024
#define DD 64
#define UU 32
#define TI 4

// Scratch (allocation-free): transposed half2-packed k' and packed q.
__device__ uint4    g_kpt[4*BB*LL];    // [(b*4+cc)*1024 + j] : u [cc*8..cc*8+7]
__device__ unsigned g_qh [BB*LL*16];   // row*16 + c : u-pair (2c, 2c+1)

__device__ __forceinline__ unsigned tanh2u(unsigned x) {
    unsigned y; asm("tanh.approx.f16x2 %0, %1;" : "=r"(y) : "r"(x)); return y;
}
__device__ __forceinline__ unsigned hadd2u(unsigned a, unsigned b) {
    __half2 r = __hadd2(reinterpret_cast<__half2&>(a), reinterpret_cast<__half2&>(b));
    return reinterpret_cast<unsigned&>(r);
}
__device__ __forceinline__ unsigned hfma2u(unsigned a, unsigned b, unsigned c) {
    __half2 r = __hfma2(reinterpret_cast<__half2&>(a), reinterpret_cast<__half2&>(b),
                        reinterpret_cast<__half2&>(c));
    return reinterpret_cast<unsigned&>(r);
}
__device__ __forceinline__ unsigned packh2(float a, float b) {
    __half2 h = __floats2half2_rn(a, b);
    return reinterpret_cast<unsigned&>(h);
}
__device__ __forceinline__ float2 h2f2(unsigned a) {
    return __half22float2(reinterpret_cast<__half2&>(a));
}
// Packed fp32x2 (Blackwell FFMA2 — only reachable via PTX)
__device__ __forceinline__ unsigned long long ffma2(
    unsigned long long a, unsigned long long b, unsigned long long c) {
    unsigned long long d;
    asm("fma.rn.f32x2 %0, %1, %2, %3;" : "=l"(d) : "l"(a), "l"(b), "l"(c));
    return d;
}
__device__ __forceinline__ unsigned long long bcast2(float p) {
    unsigned long long d;
    asm("mov.b64 %0, {%1, %1};" : "=l"(d) : "f"(p));
    return d;
}
__device__ __forceinline__ unsigned long long packf2(float a, float b) {
    unsigned long long d;
    asm("mov.b64 %0, {%1, %2};" : "=l"(d) : "f"(a), "f"(b));
    return d;
}

// ---------------------------------------------------------------------------
// Kernel 1: projections -> packed/transposed half scratch. 8 rows per block.
// ---------------------------------------------------------------------------
__global__ __launch_bounds__(256) void prep_kernel(
    const float* __restrict__ x,
    const float* __restrict__ Wt,
    const float* __restrict__ Wx,
    const float* __restrict__ bh)
{
    __shared__ float sWt[DD*UU];
    __shared__ float sWx[DD*UU];
    __shared__ float sx [8*DD];
    __shared__ float sq [8][UU];
    __shared__ float sk [8][UU];
    int t = threadIdx.x;
    for (int idx = t; idx < DD*UU; idx += 256) { sWt[idx] = Wt[idx]; sWx[idx] = Wx[idx]; }
    int row0 = blockIdx.x * 8;
    for (int idx = t; idx < 8*DD; idx += 256) sx[idx] = x[row0*DD + idx];
    __syncthreads();

    int r = t >> 5, u = t & 31;
    float aq = 0.f, ak = 0.f;
    #pragma unroll
    for (int d = 0; d < DD; d++) {
        float xv = sx[r*DD + d];
        aq = fmaf(xv, sWt[d*UU + u], aq);
        ak = fmaf(xv, sWx[d*UU + u], ak);
    }
    sq[r][u] = aq;
    sk[r][u] = ak + bh[u];
    __syncthreads();

    if (t < 128) {
        int rr = t >> 4, c = t & 15;
        g_qh[(row0 + rr)*16 + c] = packh2(sq[rr][2*c], sq[rr][2*c+1]);
    }
    if (t < 32) {
        int rr = t >> 2, cc = t & 3;
        int row = row0 + rr;
        int b = row >> 10, j = row & 1023;
        uint4 v;
        v.x = packh2(sk[rr][cc*8+0], sk[rr][cc*8+1]);
        v.y = packh2(sk[rr][cc*8+2], sk[rr][cc*8+3]);
        v.z = packh2(sk[rr][cc*8+4], sk[rr][cc*8+5]);
        v.w = packh2(sk[rr][cc*8+6], sk[rr][cc*8+7]);
        g_kpt[(b*4 + cc)*1024 + j] = v;
    }
}

// ---------------------------------------------------------------------------
// Kernel 2: fused scoring + softmax + value gather. 4 rows per block.
// Block-uniform q/Wa live in shared (LDS broadcast per chunk), not registers.
// ---------------------------------------------------------------------------
__global__ __launch_bounds__(256, 3) void attn_kernel(
    const float* __restrict__ x,
    const float* __restrict__ Wa,
    float* __restrict__ out)
{
    __shared__ float4   p_sh[LL];         // {p_row0..p_row3} per j  (16 KB)
    __shared__ float    vsh [TI*LL];      // partials: [r][g][d]     (16 KB)
    __shared__ float    redv[TI][8];
    __shared__ unsigned swa2[16];
    __shared__ unsigned sq2[TI][16];

    int t  = threadIdx.x;
    int bi = blockIdx.x;                  // 0..1023
    int b  = bi >> 8;
    int row0 = b*LL + (bi & 255)*TI;

    if (t < 16) swa2[t] = packh2(Wa[2*t], Wa[2*t+1]);
    if (t < 64) sq2[t >> 4][t & 15] = g_qh[(row0 + (t >> 4))*16 + (t & 15)];
    __syncthreads();

    const uint4* kp = g_kpt + (b*4)*1024;

    // --- Pass 1: e = sum_u Wa[u] tanh(q+k'), fp32 accum across chunks ------
    float acc_e[4][TI];                   // [jj][r]
    #pragma unroll
    for (int jj = 0; jj < 4; jj++)
        #pragma unroll
        for (int r = 0; r < TI; r++) acc_e[jj][r] = 0.f;

    #pragma unroll
    for (int cc = 0; cc < 4; cc++) {
        unsigned qc[TI][4], wc[4];
        #pragma unroll
        for (int k = 0; k < 4; k++) {
            wc[k] = swa2[cc*4 + k];
            #pragma unroll
            for (int r = 0; r < TI; r++) qc[r][k] = sq2[r][cc*4 + k];
        }
        uint4 kv[4];
        #pragma unroll
        for (int jj = 0; jj < 4; jj++) kv[jj] = kp[cc*1024 + jj*256 + t];

        #pragma unroll
        for (int jj = 0; jj < 4; jj++) {
            unsigned kw[4] = {kv[jj].x, kv[jj].y, kv[jj].z, kv[jj].w};
            #pragma unroll
            for (int r = 0; r < TI; r++) {
                unsigned hacc = 0u;
                #pragma unroll
                for (int k = 0; k < 4; k++)
                    hacc = hfma2u(tanh2u(hadd2u(qc[r][k], kw[k])), wc[k], hacc);
                float2 f = h2f2(hacc);
                acc_e[jj][r] += f.x + f.y;
            }
        }
    }

    float s[TI] = {0.f, 0.f, 0.f, 0.f};
    #pragma unroll
    for (int jj = 0; jj < 4; jj++) {
        float4 pj;
        float* pp = (float*)&pj;
        #pragma unroll
        for (int r = 0; r < TI; r++) {
            float ex = __expf(acc_e[jj][r]);   // |e| <= sum|Wa|: no max pass
            pp[r] = ex;
            s[r] += ex;
        }
        p_sh[jj*256 + t] = pj;
    }

    // --- block sum reduce (all rows) ----------------------------------------
    #pragma unroll
    for (int o = 16; o; o >>= 1)
        #pragma unroll
        for (int r = 0; r < TI; r++) s[r] += __shfl_xor_sync(0xffffffffu, s[r], o);
    if ((t & 31) == 0)
        #pragma unroll
        for (int r = 0; r < TI; r++) redv[r][t >> 5] = s[r];
    __syncthreads();                      // also orders p_sh for pass 2
    float inv[TI];
    #pragma unroll
    for (int r = 0; r < TI; r++) {
        float S = 0.f;
        #pragma unroll
        for (int w = 0; w < 8; w++) S += redv[r][w];
        inv[r] = 1.f / (S + 1e-8f);
    }

    // --- Pass 2: v[r][d] = sum_j p[r][j] * x[b,j,d] -------------------------
    int d4 = t & 15, g = t >> 4;          // 16 float4 d-lanes x 16 j-groups
    const float4* xb = (const float4*)(x + b*(LL*DD));
    unsigned long long a[TI][2];
    #pragma unroll
    for (int r = 0; r < TI; r++) { a[r][0] = 0ull; a[r][1] = 0ull; }

    #pragma unroll 4
    for (int jj = 0; jj < 64; jj++) {
        int j = jj*16 + g;                // adjacent lanes -> adjacent j rows
        float4 xv = xb[j*16 + d4];
        unsigned long long xlo = packf2(xv.x, xv.y);
        unsigned long long xhi = packf2(xv.z, xv.w);
        float4 pj = p_sh[j];
        float* pp = (float*)&pj;
        #pragma unroll
        for (int r = 0; r < TI; r++) {
            unsigned long long p2 = bcast2(pp[r]);
            a[r][0] = ffma2(p2, xlo, a[r][0]);
            a[r][1] = ffma2(p2, xhi, a[r][1]);
        }
    }
    #pragma unroll
    for (int r = 0; r < TI; r++) {
        float4 av;
        ((unsigned long long*)&av)[0] = a[r][0];
        ((unsigned long long*)&av)[1] = a[r][1];
        ((float4*)vsh)[r*256 + g*16 + d4] = av;
    }
    __syncthreads();

    // --- final combine: 256 threads = 4 rows x 64 d -------------------------
    {
        int r = t >> 6, d = t & 63;
        float v = 0.f;
        #pragma unroll
        for (int gg = 0; gg < 16; gg++) v += vsh[r*LL + gg*64 + d];
        out[(row0 + r)*DD + d] = v * inv[r];
    }
}

// ---------------------------------------------------------------------------
extern "C" void kernel_launch(void* const* d_in, const int* in_sizes, int n_in,
                              void* d_out, int out_size)
{
    const float* x  = (const float*)d_in[0];
    const float* Wt = (const float*)d_in[1];
    const float* Wx = (const float*)d_in[2];
    const float* Wa = (const float*)d_in[3];
    const float* bh = (const float*)d_in[4];
    // d_in[5] = ba cancels in softmax; d_in[6] attention_width is dead code.

    prep_kernel<<<BB*LL/8, 256>>>(x, Wt, Wx, bh);
    attn_kernel<<<BB*LL/TI, 256>>>(x, Wa, (float*)d_out);
}